// round 2
// baseline (speedup 1.0000x reference)
#include <cuda_runtime.h>

#define NX 1024
#define NY 1024
#define NB 8
#define CH (NX*NY)
#define ROWS 32
#define STRIPS (NY/ROWS)        // 32
#define NBLOCKS (STRIPS*NB)     // 256

// Physics constants
#define PR     0.71f
#define RA_PR  710.0f           // RA*PR
#define HA2_PR 71.0f            // HA^2*PR
#define PR_DA  7.1f             // PR/DA
#define DIFF_C 1.6666666666666667f
#define QQ     0.1f
#define DTINV  100.0f
#define NPTS   8388608.0

__device__ double g_partials[NBLOCKS];

// x-halo: get (x0-2, x0-1) and (x0+4, x0+5) values for center float4 via warp shuffle;
// warp-boundary lanes patch from global (L1 hit — neighbor warp just loaded it).
__device__ __forceinline__ void halo(float4 c, const float* __restrict__ rowp,
                                     int tid, int lane,
                                     float& lz, float& lw, float& rx, float& ry)
{
    lw = __shfl_up_sync(0xFFFFFFFFu, c.w, 1);
    lz = __shfl_up_sync(0xFFFFFFFFu, c.z, 1);
    rx = __shfl_down_sync(0xFFFFFFFFu, c.x, 1);
    ry = __shfl_down_sync(0xFFFFFFFFu, c.y, 1);
    if (lane == 0 && tid != 0) {
        float2 h = *(const float2*)(rowp + tid * 4 - 2);
        lz = h.x; lw = h.y;
    }
    if (lane == 31 && tid != 255) {
        float2 h = *(const float2*)(rowp + tid * 4 + 4);
        rx = h.x; ry = h.y;
    }
}

// x first+second tgrad for the 4 points of c. E = {x0-2..x0+5}.
__device__ __forceinline__ void xderiv(float4 c, float lz, float lw, float rx, float ry,
                                       int tid, float* dx, float* dxx)
{
    float E0 = lz, E1 = lw, E2 = c.x, E3 = c.y, E4 = c.z, E5 = c.w, E6 = rx, E7 = ry;
    if (tid == 0) {           // x0 == 0: i=0,1 edge forms (no left halo used)
        dx[0]  = E3 - E2;
        dx[1]  = 0.5f * (E4 - E2);
        dxx[0] = 0.5f * E4 - E3 + 0.5f * E2;
        dxx[1] = 0.25f * E5 - 0.75f * E3 + 0.5f * E2;
    } else {
        dx[0]  = 0.5f * (E3 - E1);
        dx[1]  = 0.5f * (E4 - E2);
        dxx[0] = 0.25f * (E4 - 2.0f * E2 + E0);
        dxx[1] = 0.25f * (E5 - 2.0f * E3 + E1);
    }
    if (tid == 255) {         // x0+3 == NX-1: i=NX-2,NX-1 edge forms (no right halo)
        dx[2]  = 0.5f * (E5 - E3);
        dx[3]  = E5 - E4;
        dxx[2] = 0.5f * E5 - 0.75f * E4 + 0.25f * E2;
        dxx[3] = 0.5f * E5 - E4 + 0.5f * E3;
    } else {
        dx[2]  = 0.5f * (E5 - E3);
        dx[3]  = 0.5f * (E6 - E4);
        dxx[2] = 0.25f * (E6 - 2.0f * E4 + E2);
        dxx[3] = 0.25f * (E7 - 2.0f * E5 + E3);
    }
}

__global__ __launch_bounds__(256)
void physics_loss_kernel(const float* __restrict__ fno, const float* __restrict__ fne)
{
    const int tid   = threadIdx.x;
    const int lane  = tid & 31;
    const int strip = blockIdx.x;
    const int b     = blockIdx.y;
    const int y0    = strip * ROWS;
    const int x0    = tid * 4;

    const size_t base = (size_t)b * 4 * CH;
    const float* __restrict__ Uc = fne + base;
    const float* __restrict__ Vc = fne + base + CH;
    const float* __restrict__ Tc = fne + base + 2 * (size_t)CH;
    const float* __restrict__ Pc = fne + base + 3 * (size_t)CH;
    const float* __restrict__ Uo_c = fno + base;
    const float* __restrict__ Vo_c = fno + base + CH;
    const float* __restrict__ To_c = fno + base + 2 * (size_t)CH;

    auto ld = [&](const float* __restrict__ chp, int y) -> float4 {
        y = max(0, min(y, NY - 1));
        return *(const float4*)(chp + (size_t)y * NX + x0);
    };

    // rolling windows (y-2 .. y+2) for U,V,T; (y-1 .. y+1) for P
    float4 u0 = ld(Uc, y0 - 2), u1 = ld(Uc, y0 - 1), u2 = ld(Uc, y0),
           u3 = ld(Uc, y0 + 1), u4 = ld(Uc, y0 + 2);
    float4 v0 = ld(Vc, y0 - 2), v1 = ld(Vc, y0 - 1), v2 = ld(Vc, y0),
           v3 = ld(Vc, y0 + 1), v4 = ld(Vc, y0 + 2);
    float4 t0 = ld(Tc, y0 - 2), t1 = ld(Tc, y0 - 1), t2 = ld(Tc, y0),
           t3 = ld(Tc, y0 + 1), t4 = ld(Tc, y0 + 2);
    float4 p1 = ld(Pc, y0 - 1), p2 = ld(Pc, y0), p3 = ld(Pc, y0 + 1);

    double dacc = 0.0;

    const int yend = y0 + ROWS;
    for (int y = y0; y < yend; y++) {
        // prefetch next iteration's incoming rows (y+3 / y+2)
        float4 un = ld(Uc, y + 3), vn = ld(Vc, y + 3), tn = ld(Tc, y + 3);
        float4 pn = ld(Pc, y + 2);
        // f_now center rows
        const size_t ro = (size_t)y * NX + x0;
        float4 uo4 = *(const float4*)(Uo_c + ro);
        float4 vo4 = *(const float4*)(Vo_c + ro);
        float4 to4 = *(const float4*)(To_c + ro);

        // y-derivative coefficients
        const float s1 = (y == 0 || y == NY - 1) ? 1.0f : 0.5f;
        float cm2, cm1, cc, cp1, cp2;
        if      (y == 0)      { cm2 = 0;     cm1 = 0;     cc = 0.5f;   cp1 = -1.0f; cp2 = 0.5f; }
        else if (y == 1)      { cm2 = 0;     cm1 = 0.5f;  cc = -0.75f; cp1 = 0;     cp2 = 0.25f; }
        else if (y == NY - 2) { cm2 = 0.25f; cm1 = 0;     cc = -0.75f; cp1 = 0.5f;  cp2 = 0; }
        else if (y == NY - 1) { cm2 = 0.5f;  cm1 = -1.0f; cc = 0.5f;   cp1 = 0;     cp2 = 0; }
        else                  { cm2 = 0.25f; cm1 = 0;     cc = -0.5f;  cp1 = 0;     cp2 = 0.25f; }

        // x-derivatives of center rows (shuffle halos)
        float lz, lw, rx, ry;
        float udx[4], udxx[4], vdx[4], vdxx[4], tdx[4], tdxx[4], pdx[4];
        halo(u2, Uc + (size_t)y * NX, tid, lane, lz, lw, rx, ry);
        xderiv(u2, lz, lw, rx, ry, tid, udx, udxx);
        halo(v2, Vc + (size_t)y * NX, tid, lane, lz, lw, rx, ry);
        xderiv(v2, lz, lw, rx, ry, tid, vdx, vdxx);
        halo(t2, Tc + (size_t)y * NX, tid, lane, lz, lw, rx, ry);
        xderiv(t2, lz, lw, rx, ry, tid, tdx, tdxx);
        halo(p2, Pc + (size_t)y * NX, tid, lane, lz, lw, rx, ry);
        {
            float dummy[4];
            xderiv(p2, lz, lw, rx, ry, tid, pdx, dummy);
        }

        const float* U0 = (const float*)&u0; const float* U1 = (const float*)&u1;
        const float* U2 = (const float*)&u2; const float* U3 = (const float*)&u3;
        const float* U4 = (const float*)&u4;
        const float* V0 = (const float*)&v0; const float* V1 = (const float*)&v1;
        const float* V2 = (const float*)&v2; const float* V3 = (const float*)&v3;
        const float* V4 = (const float*)&v4;
        const float* T0 = (const float*)&t0; const float* T1 = (const float*)&t1;
        const float* T2 = (const float*)&t2; const float* T3 = (const float*)&t3;
        const float* T4 = (const float*)&t4;
        const float* P1 = (const float*)&p1; const float* P3 = (const float*)&p3;
        const float* UO = (const float*)&uo4; const float* VO = (const float*)&vo4;
        const float* TO = (const float*)&to4;

        float rowacc = 0.0f;
#pragma unroll
        for (int j = 0; j < 4; j++) {
            float udy  = s1 * (U3[j] - U1[j]);
            float udyy = cm2 * U0[j] + cm1 * U1[j] + cc * U2[j] + cp1 * U3[j] + cp2 * U4[j];
            float vdy  = s1 * (V3[j] - V1[j]);
            float vdyy = cm2 * V0[j] + cm1 * V1[j] + cc * V2[j] + cp1 * V3[j] + cp2 * V4[j];
            float tdy  = s1 * (T3[j] - T1[j]);
            float tdyy = cm2 * T0[j] + cm1 * T1[j] + cc * T2[j] + cp1 * T3[j] + cp2 * T4[j];
            float pdy  = s1 * (P3[j] - P1[j]);

            float Un = U2[j], Vn = V2[j], Tn = T2[j];

            float cont = udx[j] + vdy;
            float resx = (Un - UO[j]) * DTINV + Un * udx[j] + VO[j] * udy
                         + pdx[j] - PR * (udxx[j] + udyy) + PR_DA * Un;
            float resy = (Vn - VO[j]) * DTINV + UO[j] * vdx[j] + Vn * vdy
                         + pdy - PR * (vdxx[j] + vdyy)
                         - RA_PR * Tn + (HA2_PR + PR_DA) * Vn;
            float rest = (Tn - TO[j]) * DTINV + UO[j] * tdx[j] + VO[j] * tdy
                         - DIFF_C * (tdxx[j] + tdyy) - QQ * Tn;

            rowacc += cont * cont + resx * resx + resy * resy + rest * rest;
        }
        dacc += (double)rowacc;

        // shift windows
        u0 = u1; u1 = u2; u2 = u3; u3 = u4; u4 = un;
        v0 = v1; v1 = v2; v2 = v3; v3 = v4; v4 = vn;
        t0 = t1; t1 = t2; t2 = t3; t3 = t4; t4 = tn;
        p1 = p2; p2 = p3; p3 = pn;
    }

    // block reduction
#pragma unroll
    for (int o = 16; o > 0; o >>= 1)
        dacc += __shfl_xor_sync(0xFFFFFFFFu, dacc, o);

    __shared__ double ws[8];
    if (lane == 0) ws[tid >> 5] = dacc;
    __syncthreads();
    if (tid == 0) {
        double s = 0.0;
#pragma unroll
        for (int k = 0; k < 8; k++) s += ws[k];
        g_partials[b * STRIPS + strip] = s;
    }
}

__global__ void finalize_kernel(float* __restrict__ out)
{
    const int tid = threadIdx.x;
    double v = g_partials[tid];        // NBLOCKS == blockDim == 256
#pragma unroll
    for (int o = 16; o > 0; o >>= 1)
        v += __shfl_xor_sync(0xFFFFFFFFu, v, o);
    __shared__ double ws[8];
    if ((tid & 31) == 0) ws[tid >> 5] = v;
    __syncthreads();
    if (tid == 0) {
        double s = 0.0;
#pragma unroll
        for (int k = 0; k < 8; k++) s += ws[k];
        double t = s * 1e-4 / NPTS;
        if (t < 1e-10) t = 1e-10;
        if (t > 1.0)   t = 1.0;
        out[0] = (float)t;
    }
}

extern "C" void kernel_launch(void* const* d_in, const int* in_sizes, int n_in,
                              void* d_out, int out_size)
{
    const float* f_now  = (const float*)d_in[0];
    const float* f_next = (const float*)d_in[1];

    dim3 grid(STRIPS, NB);
    physics_loss_kernel<<<grid, 256>>>(f_now, f_next);
    finalize_kernel<<<1, 256>>>((float*)d_out);
}

// round 3
// speedup vs baseline: 1.6907x; 1.6907x over previous
#include <cuda_runtime.h>

#define NX 1024
#define NY 1024
#define NB 8
#define CH (NX*NY)
#define ROWS 4
#define STRIPS (NY/ROWS)        // 256
#define NBLOCKS (STRIPS*NB)     // 2048

// Physics constants
#define PR     0.71f
#define RA_PR  710.0f           // RA*PR
#define HA2_PR 71.0f            // HA^2*PR
#define PR_DA  7.1f             // PR/DA
#define DIFF_C 1.6666666666666667f
#define QQ     0.1f
#define DTINV  100.0f
#define NPTS   8388608.0

__device__ double g_partials[NBLOCKS];

// x-halo via warp shuffle; warp-boundary lanes patch from global (L1 hit).
__device__ __forceinline__ void halo(float4 c, const float* __restrict__ rowp,
                                     int tid, int lane,
                                     float& lz, float& lw, float& rx, float& ry)
{
    lw = __shfl_up_sync(0xFFFFFFFFu, c.w, 1);
    lz = __shfl_up_sync(0xFFFFFFFFu, c.z, 1);
    rx = __shfl_down_sync(0xFFFFFFFFu, c.x, 1);
    ry = __shfl_down_sync(0xFFFFFFFFu, c.y, 1);
    if (lane == 0 && tid != 0) {
        float2 h = *(const float2*)(rowp + tid * 4 - 2);
        lz = h.x; lw = h.y;
    }
    if (lane == 31 && tid != 255) {
        float2 h = *(const float2*)(rowp + tid * 4 + 4);
        rx = h.x; ry = h.y;
    }
}

// x first+second tgrad for the 4 points of c. E = {x0-2..x0+5}.
__device__ __forceinline__ void xderiv(float4 c, float lz, float lw, float rx, float ry,
                                       int tid, float* dx, float* dxx)
{
    float E0 = lz, E1 = lw, E2 = c.x, E3 = c.y, E4 = c.z, E5 = c.w, E6 = rx, E7 = ry;
    if (tid == 0) {
        dx[0]  = E3 - E2;
        dx[1]  = 0.5f * (E4 - E2);
        dxx[0] = 0.5f * E4 - E3 + 0.5f * E2;
        dxx[1] = 0.25f * E5 - 0.75f * E3 + 0.5f * E2;
    } else {
        dx[0]  = 0.5f * (E3 - E1);
        dx[1]  = 0.5f * (E4 - E2);
        dxx[0] = 0.25f * (E4 - 2.0f * E2 + E0);
        dxx[1] = 0.25f * (E5 - 2.0f * E3 + E1);
    }
    if (tid == 255) {
        dx[2]  = 0.5f * (E5 - E3);
        dx[3]  = E5 - E4;
        dxx[2] = 0.5f * E5 - 0.75f * E4 + 0.25f * E2;
        dxx[3] = 0.5f * E5 - E4 + 0.5f * E3;
    } else {
        dx[2]  = 0.5f * (E5 - E3);
        dx[3]  = 0.5f * (E6 - E4);
        dxx[2] = 0.25f * (E6 - 2.0f * E4 + E2);
        dxx[3] = 0.25f * (E7 - 2.0f * E5 + E3);
    }
}

__global__ __launch_bounds__(256, 2)
void physics_loss_kernel(const float* __restrict__ fno, const float* __restrict__ fne)
{
    const int tid   = threadIdx.x;
    const int lane  = tid & 31;
    const int strip = blockIdx.x;
    const int b     = blockIdx.y;
    const int y0    = strip * ROWS;
    const int x0    = tid * 4;

    const size_t base = (size_t)b * 4 * CH;
    const float* __restrict__ Uc = fne + base;
    const float* __restrict__ Vc = fne + base + CH;
    const float* __restrict__ Tc = fne + base + 2 * (size_t)CH;
    const float* __restrict__ Pc = fne + base + 3 * (size_t)CH;
    const float* __restrict__ Uo_c = fno + base;
    const float* __restrict__ Vo_c = fno + base + CH;
    const float* __restrict__ To_c = fno + base + 2 * (size_t)CH;

    auto ld = [&](const float* __restrict__ chp, int y) -> float4 {
        y = max(0, min(y, NY - 1));
        return *(const float4*)(chp + (size_t)y * NX + x0);
    };

    // rolling windows (y-2 .. y+2) for U,V,T; (y-1 .. y+1) for P
    float4 u0 = ld(Uc, y0 - 2), u1 = ld(Uc, y0 - 1), u2 = ld(Uc, y0),
           u3 = ld(Uc, y0 + 1), u4 = ld(Uc, y0 + 2);
    float4 v0 = ld(Vc, y0 - 2), v1 = ld(Vc, y0 - 1), v2 = ld(Vc, y0),
           v3 = ld(Vc, y0 + 1), v4 = ld(Vc, y0 + 2);
    float4 t0 = ld(Tc, y0 - 2), t1 = ld(Tc, y0 - 1), t2 = ld(Tc, y0),
           t3 = ld(Tc, y0 + 1), t4 = ld(Tc, y0 + 2);
    float4 p1 = ld(Pc, y0 - 1), p2 = ld(Pc, y0), p3 = ld(Pc, y0 + 1);

    double dacc = 0.0;

    const int yend = y0 + ROWS;
#pragma unroll
    for (int y = y0; y < yend; y++) {
        // prefetch next iteration's incoming rows
        float4 un = ld(Uc, y + 3), vn = ld(Vc, y + 3), tn = ld(Tc, y + 3);
        float4 pn = ld(Pc, y + 2);
        // f_now center rows
        const size_t ro = (size_t)y * NX + x0;
        float4 uo4 = *(const float4*)(Uo_c + ro);
        float4 vo4 = *(const float4*)(Vo_c + ro);
        float4 to4 = *(const float4*)(To_c + ro);

        // y-derivative coefficients
        const float s1 = (y == 0 || y == NY - 1) ? 1.0f : 0.5f;
        float cm2, cm1, cc, cp1, cp2;
        if      (y == 0)      { cm2 = 0;     cm1 = 0;     cc = 0.5f;   cp1 = -1.0f; cp2 = 0.5f; }
        else if (y == 1)      { cm2 = 0;     cm1 = 0.5f;  cc = -0.75f; cp1 = 0;     cp2 = 0.25f; }
        else if (y == NY - 2) { cm2 = 0.25f; cm1 = 0;     cc = -0.75f; cp1 = 0.5f;  cp2 = 0; }
        else if (y == NY - 1) { cm2 = 0.5f;  cm1 = -1.0f; cc = 0.5f;   cp1 = 0;     cp2 = 0; }
        else                  { cm2 = 0.25f; cm1 = 0;     cc = -0.5f;  cp1 = 0;     cp2 = 0.25f; }

        // x-derivatives of center rows (shuffle halos)
        float lz, lw, rx, ry;
        float udx[4], udxx[4], vdx[4], vdxx[4], tdx[4], tdxx[4], pdx[4];
        halo(u2, Uc + (size_t)y * NX, tid, lane, lz, lw, rx, ry);
        xderiv(u2, lz, lw, rx, ry, tid, udx, udxx);
        halo(v2, Vc + (size_t)y * NX, tid, lane, lz, lw, rx, ry);
        xderiv(v2, lz, lw, rx, ry, tid, vdx, vdxx);
        halo(t2, Tc + (size_t)y * NX, tid, lane, lz, lw, rx, ry);
        xderiv(t2, lz, lw, rx, ry, tid, tdx, tdxx);
        halo(p2, Pc + (size_t)y * NX, tid, lane, lz, lw, rx, ry);
        {
            float pE0 = lz, pE1 = lw, pE2 = p2.x, pE3 = p2.y,
                  pE4 = p2.z, pE5 = p2.w, pE6 = rx, pE7 = ry;
            if (tid == 0) {
                pdx[0] = pE3 - pE2;
                pdx[1] = 0.5f * (pE4 - pE2);
            } else {
                pdx[0] = 0.5f * (pE3 - pE1);
                pdx[1] = 0.5f * (pE4 - pE2);
            }
            if (tid == 255) {
                pdx[2] = 0.5f * (pE5 - pE3);
                pdx[3] = pE5 - pE4;
            } else {
                pdx[2] = 0.5f * (pE5 - pE3);
                pdx[3] = 0.5f * (pE6 - pE4);
            }
        }

        const float* U0 = (const float*)&u0; const float* U1 = (const float*)&u1;
        const float* U2 = (const float*)&u2; const float* U3 = (const float*)&u3;
        const float* U4 = (const float*)&u4;
        const float* V0 = (const float*)&v0; const float* V1 = (const float*)&v1;
        const float* V2 = (const float*)&v2; const float* V3 = (const float*)&v3;
        const float* V4 = (const float*)&v4;
        const float* T0 = (const float*)&t0; const float* T1 = (const float*)&t1;
        const float* T2 = (const float*)&t2; const float* T3 = (const float*)&t3;
        const float* T4 = (const float*)&t4;
        const float* P1 = (const float*)&p1; const float* P3 = (const float*)&p3;
        const float* UO = (const float*)&uo4; const float* VO = (const float*)&vo4;
        const float* TO = (const float*)&to4;

        float rowacc = 0.0f;
#pragma unroll
        for (int j = 0; j < 4; j++) {
            float udy  = s1 * (U3[j] - U1[j]);
            float udyy = cm2 * U0[j] + cm1 * U1[j] + cc * U2[j] + cp1 * U3[j] + cp2 * U4[j];
            float vdy  = s1 * (V3[j] - V1[j]);
            float vdyy = cm2 * V0[j] + cm1 * V1[j] + cc * V2[j] + cp1 * V3[j] + cp2 * V4[j];
            float tdy  = s1 * (T3[j] - T1[j]);
            float tdyy = cm2 * T0[j] + cm1 * T1[j] + cc * T2[j] + cp1 * T3[j] + cp2 * T4[j];
            float pdy  = s1 * (P3[j] - P1[j]);

            float Un = U2[j], Vn = V2[j], Tn = T2[j];

            float cont = udx[j] + vdy;
            float resx = (Un - UO[j]) * DTINV + Un * udx[j] + VO[j] * udy
                         + pdx[j] - PR * (udxx[j] + udyy) + PR_DA * Un;
            float resy = (Vn - VO[j]) * DTINV + UO[j] * vdx[j] + Vn * vdy
                         + pdy - PR * (vdxx[j] + vdyy)
                         - RA_PR * Tn + (HA2_PR + PR_DA) * Vn;
            float rest = (Tn - TO[j]) * DTINV + UO[j] * tdx[j] + VO[j] * tdy
                         - DIFF_C * (tdxx[j] + tdyy) - QQ * Tn;

            rowacc += cont * cont + resx * resx + resy * resy + rest * rest;
        }
        dacc += (double)rowacc;

        // shift windows
        u0 = u1; u1 = u2; u2 = u3; u3 = u4; u4 = un;
        v0 = v1; v1 = v2; v2 = v3; v3 = v4; v4 = vn;
        t0 = t1; t1 = t2; t2 = t3; t3 = t4; t4 = tn;
        p1 = p2; p2 = p3; p3 = pn;
    }

    // block reduction
#pragma unroll
    for (int o = 16; o > 0; o >>= 1)
        dacc += __shfl_xor_sync(0xFFFFFFFFu, dacc, o);

    __shared__ double ws[8];
    if (lane == 0) ws[tid >> 5] = dacc;
    __syncthreads();
    if (tid == 0) {
        double s = 0.0;
#pragma unroll
        for (int k = 0; k < 8; k++) s += ws[k];
        g_partials[(size_t)b * STRIPS + strip] = s;
    }
}

__global__ __launch_bounds__(1024)
void finalize_kernel(float* __restrict__ out)
{
    const int tid = threadIdx.x;
    double v = g_partials[tid] + g_partials[tid + 1024];   // NBLOCKS == 2048
#pragma unroll
    for (int o = 16; o > 0; o >>= 1)
        v += __shfl_xor_sync(0xFFFFFFFFu, v, o);
    __shared__ double ws[32];
    if ((tid & 31) == 0) ws[tid >> 5] = v;
    __syncthreads();
    if (tid == 0) {
        double s = 0.0;
#pragma unroll
        for (int k = 0; k < 32; k++) s += ws[k];
        double t = s * 1e-4 / NPTS;
        if (t < 1e-10) t = 1e-10;
        if (t > 1.0)   t = 1.0;
        out[0] = (float)t;
    }
}

extern "C" void kernel_launch(void* const* d_in, const int* in_sizes, int n_in,
                              void* d_out, int out_size)
{
    const float* f_now  = (const float*)d_in[0];
    const float* f_next = (const float*)d_in[1];

    dim3 grid(STRIPS, NB);
    physics_loss_kernel<<<grid, 256>>>(f_now, f_next);
    finalize_kernel<<<1, 1024>>>((float*)d_out);
}